// round 8
// baseline (speedup 1.0000x reference)
#include <cuda_runtime.h>

#define Wd 192
#define Hd 192
#define HW (Wd * Hd)
#define Hm 190
#define Wm 190
#define NBG 32     // B*G = 2*16
#define SPLIT 10
#define RS 19      // rows per strip (190/10)
#define TROWS (RS + 2)          // tile rows per plane (19 + 2 border)
#define PLSTRIDE (TROWS * Wd)   // floats per plane tile

// Scratch (device globals; no runtime allocation)
__device__ double g_part[288 * SPLIT * 36];  // partial triangular grams
__device__ int    g_nnA[NBG * 9];
__device__ int    g_nnK[NBG * 9];
__device__ float  g_cnt[NBG * 9];

// ---------------------------------------------------------------------------
// Kernel A: per (bg, j, strip) partial 8x8 gram of motif rows.
// Motif row c -> flat F=8j+c -> (a=F/9, k=F%9); value = feat[a, k/3+y, k%3+x].
// The 8 rows span at most 2 adjacent planes -> stage both in smem, 8 LDS/pos.
// ---------------------------------------------------------------------------
__global__ __launch_bounds__(192) void motif_gram_kernel(const float* __restrict__ f) {
    const int blk   = blockIdx.x;     // 0..287 = bg*9 + j
    const int strip = blockIdx.y;     // 0..9
    const int bg    = blk / 9;
    const int j     = blk % 9;
    const float* fb = f + (size_t)bg * 8 * HW;

    const int a_lo = (8 * j) / 9;
    const int a_hi = (8 * j + 7) / 9;   // a_lo or a_lo+1
    const int a1   = a_hi;              // second plane to stage

    int offc[8];
#pragma unroll
    for (int c = 0; c < 8; c++) {
        const int F = 8 * j + c;
        const int a = F / 9, k = F % 9;
        offc[c] = (a - a_lo) * PLSTRIDE + (k / 3) * Wd + (k % 3);
    }

    __shared__ float tile[2 * PLSTRIDE];         // 2*21*192*4 = 32256 B
    __shared__ float part[6][36];

    // Stage 2 planes x TROWS rows x 192 floats via float4 (all aligned).
    const int y0 = strip * RS;
    const int NV4 = 2 * TROWS * (Wd / 4);        // 2016 float4s
    {
        float4* t4 = (float4*)tile;
        for (int i = threadIdx.x; i < NV4; i += 192) {
            const int pl = i / (TROWS * (Wd / 4));
            const int rem = i - pl * (TROWS * (Wd / 4));
            const int rr = rem / (Wd / 4);
            const int c4 = rem - rr * (Wd / 4);
            const int a = pl ? a1 : a_lo;
            const float4* src = (const float4*)(fb + (size_t)a * HW + (y0 + rr) * Wd) + c4;
            t4[i] = *src;
        }
    }
    __syncthreads();

    float acc[36];
#pragma unroll
    for (int t = 0; t < 36; t++) acc[t] = 0.f;

    const int x = threadIdx.x;
    if (x < Wm) {
#pragma unroll 1
        for (int r = 0; r < RS; r++) {
            const int base = r * Wd + x;
            float m[8];
#pragma unroll
            for (int c = 0; c < 8; c++) m[c] = tile[offc[c] + base];
            int t = 0;
#pragma unroll
            for (int c = 0; c < 8; c++)
#pragma unroll
                for (int d = c; d < 8; d++) {
                    acc[t] += m[c] * m[d];
                    t++;
                }
        }
    }

    // warp shuffle reduce (6 full warps), cross-warp in double
    const int lane = threadIdx.x & 31, wid = threadIdx.x >> 5;
#pragma unroll
    for (int t = 0; t < 36; t++) {
#pragma unroll
        for (int sh = 16; sh > 0; sh >>= 1)
            acc[t] += __shfl_down_sync(0xffffffffu, acc[t], sh);
    }
    if (lane == 0) {
#pragma unroll
        for (int t = 0; t < 36; t++) part[wid][t] = acc[t];
    }
    __syncthreads();

    if (threadIdx.x < 36) {
        double s = 0.0;
#pragma unroll
        for (int w6 = 0; w6 < 6; w6++) s += (double)part[w6][threadIdx.x];
        g_part[((size_t)blk * SPLIT + strip) * 36 + threadIdx.x] = s;
    }
}

// ---------------------------------------------------------------------------
// Kernel B: reduce strip partials -> grams; argmin (diag excluded, first-min
// tie-break); per j: u = max nn, cnt = #{nn==u}.
// ---------------------------------------------------------------------------
__global__ __launch_bounds__(128) void motif_argmin_kernel() {
    const int bg = blockIdx.x;
    const int t  = threadIdx.x;
    __shared__ double G[9 * 64];
    __shared__ int nn[72];

    for (int e = t; e < 9 * 36; e += 128) {
        const int j = e / 36;
        int rem = e % 36, c = 0;
        while (rem >= 8 - c) { rem -= (8 - c); c++; }
        const int d = c + rem;
        double sum = 0.0;
#pragma unroll
        for (int sl = 0; sl < SPLIT; sl++)
            sum += g_part[((size_t)(bg * 9 + j) * SPLIT + sl) * 36 + (e % 36)];
        G[j * 64 + c * 8 + d] = sum;
        G[j * 64 + d * 8 + c] = sum;
    }
    __syncthreads();

    if (t < 72) {
        const int j = t / 8, c = t % 8;
        const double* gj = G + j * 64;
        const double scc = gj[c * 8 + c];
        double best = 1e300;
        int bi = 0;
        for (int d = 0; d < 8; d++) {
            if (d == c) continue;
            const double d2 = scc + gj[d * 8 + d] - 2.0 * gj[c * 8 + d];
            if (d2 < best) { best = d2; bi = d; }
        }
        nn[t] = bi;
    }
    __syncthreads();

    if (t < 9) {
        int u = 0, cnt = 0;
        for (int c = 0; c < 8; c++) u = max(u, nn[t * 8 + c]);
        for (int c = 0; c < 8; c++) cnt += (nn[t * 8 + c] == u) ? 1 : 0;
        const int fn = 8 * t + u;
        g_nnA[bg * 9 + t] = fn / 9;
        g_nnK[bg * 9 + t] = fn % 9;
        g_cnt[bg * 9 + t] = (float)cnt;
    }
}

// ---------------------------------------------------------------------------
// Kernel C: gather form of the fold. Grid (256 planes, 4 row-strips of 48).
// Thread = column x; row loop; all loads coalesced.
// out[h,w] = mask*nvalid*self + sum over valid knew of
//            floor(((self * nb) * cnt_j) * 0.125f)
// ---------------------------------------------------------------------------
__global__ __launch_bounds__(192) void motif_out_kernel(const float* __restrict__ f,
                                                        float* __restrict__ out) {
    const int bc = blockIdx.x;        // b*128 + cglob
    const int b = bc >> 7, cglob = bc & 127;
    const int g = cglob >> 3, cnew = cglob & 7;
    const int bg = b * 16 + g;

    __shared__ int   off9[9];
    __shared__ float cnt9[9];
    if (threadIdx.x < 9) {
        const int knew = threadIdx.x;
        const int j = (cnew * 9 + knew) >> 3;
        const int an = g_nnA[bg * 9 + j];
        const int kn = g_nnK[bg * 9 + j];
        cnt9[knew] = g_cnt[bg * 9 + j];
        const int dh = kn / 3 - knew / 3;
        const int dw = kn % 3 - knew % 3;
        off9[knew] = (an - cnew) * HW + dh * Wd + dw;
    }
    __syncthreads();

    const float* fc = f + (size_t)bc * HW;
    float* oc = out + (size_t)bc * HW;
    const float mask = (b != 0) ? 1.0f : 0.0f;

    const int x = threadIdx.x;
    const bool xin = (x >= 2 && x <= Wd - 3);
    const int kjLo = max(0, x - (Wm - 1)), kjHi = min(2, x);
    const int r0 = blockIdx.y * 48;

#pragma unroll 2
    for (int r = r0; r < r0 + 48; r++) {
        const int idx = r * Wd + x;
        const float self = fc[idx];
        float acc = 0.f;
        int nvalid;

        if (r >= 2 && r <= Hd - 3 && xin) {
            nvalid = 9;
#pragma unroll
            for (int k = 0; k < 9; k++) {
                const float nb = fc[idx + off9[k]];
                float tv = self * nb;     // exact op order matches reference
                tv = tv * cnt9[k];
                tv = tv * 0.125f;         // /8 exact
                acc += floorf(tv);
            }
        } else {
            const int kiLo = max(0, r - (Hm - 1)), kiHi = min(2, r);
            nvalid = (kiHi - kiLo + 1) * (kjHi - kjLo + 1);
            for (int ki = kiLo; ki <= kiHi; ki++)
                for (int kj = kjLo; kj <= kjHi; kj++) {
                    const int k = ki * 3 + kj;
                    const float nb = fc[idx + off9[k]];
                    float tv = self * nb;
                    tv = tv * cnt9[k];
                    tv = tv * 0.125f;
                    acc += floorf(tv);
                }
        }
        oc[idx] = acc + mask * (float)nvalid * self;
    }
}

extern "C" void kernel_launch(void* const* d_in, const int* in_sizes, int n_in,
                              void* d_out, int out_size) {
    const float* f = (const float*)d_in[0];
    float* out = (float*)d_out;
    (void)in_sizes; (void)n_in; (void)out_size;

    motif_gram_kernel<<<dim3(288, SPLIT), 192>>>(f);
    motif_argmin_kernel<<<32, 128>>>();
    motif_out_kernel<<<dim3(256, 4), 192>>>(f, out);
}

// round 9
// speedup vs baseline: 1.2686x; 1.2686x over previous
#include <cuda_runtime.h>

#define Wd 192
#define Hd 192
#define HW (Wd * Hd)
#define Hm 190
#define Wm 190
#define NBG 32     // B*G = 2*16
#define SPLIT 10
#define RS 19      // rows per strip (190/10)
#define TROWS (RS + 2)          // tile rows per plane (19 + 2 border)
#define PLSTRIDE (TROWS * Wd)   // floats per plane tile

// Scratch (device globals; no runtime allocation)
__device__ double g_part[288 * SPLIT * 36];  // partial triangular grams
__device__ int    g_nnA[NBG * 9];
__device__ int    g_nnK[NBG * 9];
__device__ float  g_cnt[NBG * 9];

// ---------------------------------------------------------------------------
// Kernel A: per (bg, j, strip) partial 8x8 gram of motif rows.
// Motif row c -> flat F=8j+c -> (a=F/9, k=F%9); value = feat[a, k/3+y, k%3+x].
// The 8 rows span at most 2 adjacent planes -> stage them in smem.
// J is a compile-time constant so all LDS offsets fold into immediates.
// ---------------------------------------------------------------------------
template<int J>
__device__ __forceinline__ void gram_body(const float* __restrict__ fb,
                                          const int strip, const int blk,
                                          float* __restrict__ tile,
                                          float (*part)[36]) {
    constexpr int A_LO = (8 * J) / 9;
    constexpr int A_HI = (8 * J + 7) / 9;
    constexpr int NPL  = (A_HI == A_LO) ? 1 : 2;

    // Stage NPL planes x TROWS rows x 192 floats via float4 (all aligned).
    const int y0 = strip * RS;
    constexpr int V4_PER_PL = TROWS * (Wd / 4);
    {
        float4* t4 = (float4*)tile;
        for (int i = threadIdx.x; i < NPL * V4_PER_PL; i += 192) {
            const int pl  = i / V4_PER_PL;
            const int rem = i - pl * V4_PER_PL;
            const int rr  = rem / (Wd / 4);
            const int c4  = rem - rr * (Wd / 4);
            const float4* src =
                (const float4*)(fb + (size_t)(A_LO + pl) * HW + (y0 + rr) * Wd) + c4;
            t4[i] = *src;
        }
    }
    __syncthreads();

    float acc[36];
#pragma unroll
    for (int t = 0; t < 36; t++) acc[t] = 0.f;

    const int x = threadIdx.x;
    if (x < Wm) {
        int base = x;
#pragma unroll 1
        for (int r = 0; r < RS; r++) {
            float m[8];
#pragma unroll
            for (int c = 0; c < 8; c++) {
                const int F = 8 * J + c;          // compile-time
                const int a = F / 9, k = F % 9;   // compile-time
                m[c] = tile[(a - A_LO) * PLSTRIDE + (k / 3) * Wd + (k % 3) + base];
            }
            int t = 0;
#pragma unroll
            for (int c = 0; c < 8; c++)
#pragma unroll
                for (int d = c; d < 8; d++) {
                    acc[t] += m[c] * m[d];
                    t++;
                }
            base += Wd;
        }
    }

    // warp shuffle reduce (6 full warps), cross-warp in double
    const int lane = threadIdx.x & 31, wid = threadIdx.x >> 5;
#pragma unroll
    for (int t = 0; t < 36; t++) {
#pragma unroll
        for (int sh = 16; sh > 0; sh >>= 1)
            acc[t] += __shfl_down_sync(0xffffffffu, acc[t], sh);
    }
    if (lane == 0) {
#pragma unroll
        for (int t = 0; t < 36; t++) part[wid][t] = acc[t];
    }
    __syncthreads();

    if (threadIdx.x < 36) {
        double s = 0.0;
#pragma unroll
        for (int w6 = 0; w6 < 6; w6++) s += (double)part[w6][threadIdx.x];
        g_part[((size_t)blk * SPLIT + strip) * 36 + threadIdx.x] = s;
    }
}

__global__ __launch_bounds__(192) void motif_gram_kernel(const float* __restrict__ f) {
    const int blk   = blockIdx.x;     // 0..287 = bg*9 + j
    const int strip = blockIdx.y;     // 0..9
    const int bg    = blk / 9;
    const int j     = blk % 9;
    const float* fb = f + (size_t)bg * 8 * HW;

    __shared__ float tile[2 * PLSTRIDE];   // 32256 B
    __shared__ float part[6][36];

    switch (j) {   // block-uniform branch
        case 0: gram_body<0>(fb, strip, blk, tile, part); break;
        case 1: gram_body<1>(fb, strip, blk, tile, part); break;
        case 2: gram_body<2>(fb, strip, blk, tile, part); break;
        case 3: gram_body<3>(fb, strip, blk, tile, part); break;
        case 4: gram_body<4>(fb, strip, blk, tile, part); break;
        case 5: gram_body<5>(fb, strip, blk, tile, part); break;
        case 6: gram_body<6>(fb, strip, blk, tile, part); break;
        case 7: gram_body<7>(fb, strip, blk, tile, part); break;
        default: gram_body<8>(fb, strip, blk, tile, part); break;
    }
}

// ---------------------------------------------------------------------------
// Kernel B: reduce strip partials -> grams; argmin (diag excluded, first-min
// tie-break); per j: u = max nn, cnt = #{nn==u}.
// ---------------------------------------------------------------------------
__global__ __launch_bounds__(128) void motif_argmin_kernel() {
    const int bg = blockIdx.x;
    const int t  = threadIdx.x;
    __shared__ double G[9 * 64];
    __shared__ int nn[72];

    for (int e = t; e < 9 * 36; e += 128) {
        const int j = e / 36;
        int rem = e % 36, c = 0;
        while (rem >= 8 - c) { rem -= (8 - c); c++; }
        const int d = c + rem;
        double sum = 0.0;
#pragma unroll
        for (int sl = 0; sl < SPLIT; sl++)
            sum += g_part[((size_t)(bg * 9 + j) * SPLIT + sl) * 36 + (e % 36)];
        G[j * 64 + c * 8 + d] = sum;
        G[j * 64 + d * 8 + c] = sum;
    }
    __syncthreads();

    if (t < 72) {
        const int j = t / 8, c = t % 8;
        const double* gj = G + j * 64;
        const double scc = gj[c * 8 + c];
        double best = 1e300;
        int bi = 0;
        for (int d = 0; d < 8; d++) {
            if (d == c) continue;
            const double d2 = scc + gj[d * 8 + d] - 2.0 * gj[c * 8 + d];
            if (d2 < best) { best = d2; bi = d; }
        }
        nn[t] = bi;
    }
    __syncthreads();

    if (t < 9) {
        int u = 0, cnt = 0;
        for (int c = 0; c < 8; c++) u = max(u, nn[t * 8 + c]);
        for (int c = 0; c < 8; c++) cnt += (nn[t * 8 + c] == u) ? 1 : 0;
        const int fn = 8 * t + u;
        g_nnA[bg * 9 + t] = fn / 9;
        g_nnK[bg * 9 + t] = fn % 9;
        g_cnt[bg * 9 + t] = (float)cnt;
    }
}

// ---------------------------------------------------------------------------
// Kernel C (R7 version — empirically fast): gather form of the fold.
// Grid (256 planes, 4 flat chunks). out[h,w] = mask*nvalid*self +
//   sum over valid knew of floor(((self * nb) * cnt_j) * 0.125f)
// ---------------------------------------------------------------------------
__global__ __launch_bounds__(256) void motif_out_kernel(const float* __restrict__ f,
                                                        float* __restrict__ out) {
    const int bc = blockIdx.x;        // b*128 + cglob
    const int b = bc >> 7, cglob = bc & 127;
    const int g = cglob >> 3, cnew = cglob & 7;
    const int bg = b * 16 + g;

    __shared__ int   off9[9];
    __shared__ float cnt9[9];
    if (threadIdx.x < 9) {
        const int knew = threadIdx.x;
        const int j = (cnew * 9 + knew) >> 3;
        const int an = g_nnA[bg * 9 + j];
        const int kn = g_nnK[bg * 9 + j];
        cnt9[knew] = g_cnt[bg * 9 + j];
        const int dh = kn / 3 - knew / 3;
        const int dw = kn % 3 - knew % 3;
        off9[knew] = (an - cnew) * HW + dh * Wd + dw;
    }
    __syncthreads();

    const float* fc = f + (size_t)bc * HW;
    float* oc = out + (size_t)bc * HW;
    const float mask = (b != 0) ? 1.0f : 0.0f;

    const int start = blockIdx.y * (HW / 4);
    const int end   = start + (HW / 4);

    for (int idx = start + threadIdx.x; idx < end; idx += 256) {
        const int h = idx / Wd;
        const int w = idx - h * Wd;
        const float self = fc[idx];
        float acc = 0.f;
        int nvalid;

        if (h >= 2 && h <= Hd - 3 && w >= 2 && w <= Wd - 3) {
            nvalid = 9;
#pragma unroll
            for (int k = 0; k < 9; k++) {
                const float nb = fc[idx + off9[k]];
                float tv = self * nb;     // exact op order matches reference
                tv = tv * cnt9[k];
                tv = tv * 0.125f;         // /8 exact
                acc += floorf(tv);
            }
        } else {
            const int kiLo = max(0, h - (Hm - 1)), kiHi = min(2, h);
            const int kjLo = max(0, w - (Wm - 1)), kjHi = min(2, w);
            nvalid = (kiHi - kiLo + 1) * (kjHi - kjLo + 1);
            for (int ki = kiLo; ki <= kiHi; ki++)
                for (int kj = kjLo; kj <= kjHi; kj++) {
                    const int k = ki * 3 + kj;
                    const float nb = fc[idx + off9[k]];
                    float tv = self * nb;
                    tv = tv * cnt9[k];
                    tv = tv * 0.125f;
                    acc += floorf(tv);
                }
        }
        oc[idx] = acc + mask * (float)nvalid * self;
    }
}

extern "C" void kernel_launch(void* const* d_in, const int* in_sizes, int n_in,
                              void* d_out, int out_size) {
    const float* f = (const float*)d_in[0];
    float* out = (float*)d_out;
    (void)in_sizes; (void)n_in; (void)out_size;

    motif_gram_kernel<<<dim3(288, SPLIT), 192>>>(f);
    motif_argmin_kernel<<<32, 128>>>();
    motif_out_kernel<<<dim3(256, 4), 256>>>(f, out);
}